// round 5
// baseline (speedup 1.0000x reference)
#include <cuda_runtime.h>
#include <math.h>

// ConfidenceCalibration: softmax over bins sums to 1, so
// final = clip(sigmoid(mean(x,-1)) * bin_scaling[bucketize(...)], 0, 1).
// Pure HBM-streaming row reduction: 128 MB read once.
//
// R3/R4: persistent grid-stride kernel. R2 was 4096 short-lived CTAs
// (one row per warp, exit) -> multi-CTA spread + wave-transition overhead
// capped DRAM at 70%. Now 1024 CTAs, each warp loops over 4 rows, single
// wave, long T_CTA -> spread amortizes to floor. (R4 = R3 re-bench after
// infra failure, with pointer-increment loop instead of per-iter IMAD.)

__device__ __forceinline__ float warp_reduce_sum(float s) {
    #pragma unroll
    for (int o = 16; o; o >>= 1) s += __shfl_xor_sync(0xffffffffu, s, o);
    return s;
}

__device__ __forceinline__ void finalize(float s, float invD, int NB,
                                         const float* __restrict__ bin_scaling,
                                         float* __restrict__ out, int row) {
    float mean = s * invD;
    float base = 1.0f / (1.0f + expf(-mean));
    // searchsorted(linspace(0,1,NB+1), base, 'right') - 1
    int idx = -1;
    for (int i = 0; i <= NB; i++) {
        float bnd = (float)i / (float)NB;
        if (bnd <= base) idx = i; else break;
    }
    float scale = (idx >= 0 && idx < NB) ? bin_scaling[idx] : 0.0f;
    out[row] = fminf(fmaxf(base * scale, 0.0f), 1.0f);
}

// Persistent, specialized D == 1024 (8 x float4 per lane, front-batched).
__global__ void __launch_bounds__(256) confcal_persist_1024(
        const float* __restrict__ x,
        const float* __restrict__ bin_scaling,
        float* __restrict__ out,
        int B, int NB, int total_warps) {
    const int warp = (blockIdx.x * blockDim.x + threadIdx.x) >> 5;
    const int lane = threadIdx.x & 31;

    // Row stride in float4 units: total_warps rows * 256 float4/row.
    const size_t stride4 = (size_t)total_warps * 256u;
    const float4* p = reinterpret_cast<const float4*>(x) + (size_t)warp * 256u + lane;

    for (int row = warp; row < B; row += total_warps, p += stride4) {
        // 8 independent streaming loads, all in flight before arithmetic.
        float4 v0 = __ldcs(p + 0 * 32);
        float4 v1 = __ldcs(p + 1 * 32);
        float4 v2 = __ldcs(p + 2 * 32);
        float4 v3 = __ldcs(p + 3 * 32);
        float4 v4 = __ldcs(p + 4 * 32);
        float4 v5 = __ldcs(p + 5 * 32);
        float4 v6 = __ldcs(p + 6 * 32);
        float4 v7 = __ldcs(p + 7 * 32);

        float a0 = (v0.x + v0.y) + (v0.z + v0.w);
        float a1 = (v1.x + v1.y) + (v1.z + v1.w);
        float a2 = (v2.x + v2.y) + (v2.z + v2.w);
        float a3 = (v3.x + v3.y) + (v3.z + v3.w);
        float a4 = (v4.x + v4.y) + (v4.z + v4.w);
        float a5 = (v5.x + v5.y) + (v5.z + v5.w);
        float a6 = (v6.x + v6.y) + (v6.z + v6.w);
        float a7 = (v7.x + v7.y) + (v7.z + v7.w);
        float s = ((a0 + a1) + (a2 + a3)) + ((a4 + a5) + (a6 + a7));

        s = warp_reduce_sum(s);
        if (lane == 0) finalize(s, 1.0f / 1024.0f, NB, bin_scaling, out, row);
    }
}

// Generic fallback (any D), persistent grid-stride.
__global__ void confcal_persist_gen(const float* __restrict__ x,
                                    const float* __restrict__ bin_scaling,
                                    float* __restrict__ out,
                                    int B, int D, int NB, int total_warps) {
    const int warp = (blockIdx.x * blockDim.x + threadIdx.x) >> 5;
    const int lane = threadIdx.x & 31;
    const int nvec = D >> 2;

    for (int row = warp; row < B; row += total_warps) {
        const float* rowp = x + (size_t)row * (size_t)D;
        const float4* row4 = reinterpret_cast<const float4*>(rowp);

        float s = 0.0f;
        #pragma unroll 8
        for (int i = lane; i < nvec; i += 32) {
            float4 v = __ldcs(row4 + i);
            s += (v.x + v.y) + (v.z + v.w);
        }
        for (int i = (nvec << 2) + lane; i < D; i += 32) s += rowp[i];

        s = warp_reduce_sum(s);
        if (lane == 0) finalize(s, 1.0f / (float)D, NB, bin_scaling, out, row);
    }
}

extern "C" void kernel_launch(void* const* d_in, const int* in_sizes, int n_in,
                              void* d_out, int out_size) {
    const float* x           = (const float*)d_in[0];
    const float* bin_scaling = (const float*)d_in[7];
    float* out = (float*)d_out;

    const int B  = out_size;            // 32768
    const int D  = in_sizes[0] / B;     // 1024
    const int NB = in_sizes[7];         // 15

    const int threads = 256;
    const int blocks  = 1024;           // single wave: ~7 CTAs/SM on 148-152 SMs
    const int total_warps = blocks * (threads / 32);   // 8192 -> 4 rows/warp

    if (D == 1024) {
        confcal_persist_1024<<<blocks, threads>>>(x, bin_scaling, out, B, NB, total_warps);
    } else {
        confcal_persist_gen<<<blocks, threads>>>(x, bin_scaling, out, B, D, NB, total_warps);
    }
}